// round 8
// baseline (speedup 1.0000x reference)
#include <cuda_runtime.h>

#define N_STRUCT_MAX 16384

__device__ __align__(16) float g_cinv[N_STRUCT_MAX * 12];
__device__ __align__(16) float g_cvec[N_STRUCT_MAX * 32];

__device__ __forceinline__ float leaky(float x) { return fmaxf(x, 0.01f * x); }

__device__ __forceinline__ unsigned long long pack2(float lo, float hi) {
    unsigned long long r;
    asm("mov.b64 %0, {%1, %2};" : "=l"(r) : "f"(lo), "f"(hi));
    return r;
}
__device__ __forceinline__ void unpack2(unsigned long long v, float& lo, float& hi) {
    asm("mov.b64 {%0, %1}, %2;" : "=f"(lo), "=f"(hi) : "l"(v));
}
__device__ __forceinline__ unsigned long long fma2(unsigned long long a, unsigned long long b,
                                                   unsigned long long c) {
    unsigned long long d;
    asm("fma.rn.f32x2 %0, %1, %2, %3;" : "=l"(d) : "l"(a), "l"(b), "l"(c));
    return d;
}

// One warp per structure.
__global__ __launch_bounds__(256) void precompute_kernel(
    const float* __restrict__ cell,
    const float* __restrict__ w2a,
    const float* __restrict__ b2a,
    float* __restrict__ out, int S)
{
    __shared__ float sW[81 * 32];  // [t][j] = w2a[j*90+9+t]
    int tid = threadIdx.x;
    for (int i = tid; i < 81 * 32; i += blockDim.x) {
        int t = i >> 5, j = i & 31;
        sW[i] = w2a[j * 90 + 9 + t];
    }
    __syncthreads();

    int warpId = tid >> 5;
    int lane = tid & 31;
    int s = blockIdx.x * 8 + warpId;
    if (s >= S) return;

    float m[9];
#pragma unroll
    for (int i = 0; i < 9; i++) m[i] = __ldg(cell + s * 9 + i);

    float acc = b2a[lane];
#pragma unroll
    for (int p = 0; p < 9; p++) {
        float mp = m[p];
#pragma unroll
        for (int q = 0; q < 9; q++)
            acc = fmaf(sW[(p * 9 + q) * 32 + lane], mp * m[q], acc);
    }
    g_cvec[s * 32 + lane] = acc;

    if (lane < 6) out[s * 6 + lane] = 0.f;

    if (lane == 0) {
        float c00 = m[4] * m[8] - m[5] * m[7];
        float c01 = m[5] * m[6] - m[3] * m[8];
        float c02 = m[3] * m[7] - m[4] * m[6];
        float det = m[0] * c00 + m[1] * c01 + m[2] * c02;
        float id = 1.f / det;
        float4* o = (float4*)(g_cinv + s * 12);
        float4 r0, r1, r2;
        r0.x = c00 * id;
        r0.y = (m[2] * m[7] - m[1] * m[8]) * id;
        r0.z = (m[1] * m[5] - m[2] * m[4]) * id;
        r0.w = c01 * id;
        r1.x = (m[0] * m[8] - m[2] * m[6]) * id;
        r1.y = (m[2] * m[3] - m[0] * m[5]) * id;
        r1.z = c02 * id;
        r1.w = (m[1] * m[6] - m[0] * m[7]) * id;
        r2.x = (m[0] * m[4] - m[1] * m[3]) * id;
        r2.y = 0.f; r2.z = 0.f; r2.w = 0.f;
        o[0] = r0; o[1] = r1; o[2] = r2;
    }
}

// 4 atoms per thread: weight LDS stream amortized 4x.
__global__ void __launch_bounds__(128, 3) atom_kernel(
    const float* __restrict__ atom_prop, const float* __restrict__ pos,
    const int* __restrict__ batch,
    const float* __restrict__ w0, const float* __restrict__ b0,
    const float* __restrict__ w1, const float* __restrict__ b1,
    const float* __restrict__ w1n, const float* __restrict__ b1n,
    const float* __restrict__ w2a,
    const float* __restrict__ w2b, const float* __restrict__ b2b,
    const float* __restrict__ w2c, const float* __restrict__ b2c,
    float* __restrict__ out, int n)
{
    __shared__ __align__(16) float sW1t[9 * 32];   // [k][j]
    __shared__ __align__(16) float sW2t[32 * 16];  // [k][j]
    __shared__ __align__(16) float sW3t[16 * 8];   // [k][j], row padded to 8 (6 used)
    __shared__ float sSmall[64];

    int tid = threadIdx.x;
    for (int i = tid; i < 288; i += blockDim.x) {
        int k = i >> 5, j = i & 31;
        sW1t[i] = w2a[j * 90 + k];
    }
    for (int i = tid; i < 512; i += blockDim.x) {
        int k = i >> 4, j = i & 15;
        sW2t[i] = w2b[j * 32 + k];
    }
    for (int i = tid; i < 128; i += blockDim.x) {
        int k = i >> 3, j = i & 7;
        sW3t[i] = (j < 6) ? w2c[j * 16 + k] : 0.f;
    }
    if (tid < 9)        sSmall[tid] = w0[tid];
    else if (tid < 18)  sSmall[tid] = w1[tid - 9];
    else if (tid < 27)  sSmall[tid] = w1n[tid - 18];
    else if (tid < 30)  sSmall[tid] = b0[tid - 27];
    else if (tid < 33)  sSmall[tid] = b1[tid - 30];
    else if (tid < 36)  sSmall[tid] = b1n[tid - 33];
    else if (tid < 52)  sSmall[tid] = b2b[tid - 36];
    else if (tid < 60)  sSmall[tid] = (tid < 58) ? b2c[tid - 52] : 0.f;
    __syncthreads();

    const float* sw0  = sSmall;
    const float* sw1  = sSmall + 9;
    const float* sw1n = sSmall + 18;
    const float* sb0  = sSmall + 27;
    const float* sb1  = sSmall + 30;
    const float* sb1n = sSmall + 33;
    const float* sb2b = sSmall + 36;
    const float* sb2c = sSmall + 52;

    int lane = tid & 31;
    int i0 = (blockIdx.x * blockDim.x + tid) * 4;
    bool full = (i0 + 3) < n;
    int nval = n - i0;                  // #valid atoms (clamp below)
    if (nval > 4) nval = 4;
    if (nval < 0) nval = 0;

    int kk[4];
    float P[4][3], AP[4][3];
    if (full) {
        int4 kv = *(const int4*)(batch + i0);
        kk[0] = kv.x; kk[1] = kv.y; kk[2] = kv.z; kk[3] = kv.w;
        const float4* pp = (const float4*)(pos + 3 * i0);
        float4 p0 = pp[0], p1 = pp[1], p2 = pp[2];
        const float4* aa = (const float4*)(atom_prop + 3 * i0);
        float4 a0 = aa[0], a1 = aa[1], a2 = aa[2];
        P[0][0]=p0.x; P[0][1]=p0.y; P[0][2]=p0.z;
        P[1][0]=p0.w; P[1][1]=p1.x; P[1][2]=p1.y;
        P[2][0]=p1.z; P[2][1]=p1.w; P[2][2]=p2.x;
        P[3][0]=p2.y; P[3][1]=p2.z; P[3][2]=p2.w;
        AP[0][0]=a0.x; AP[0][1]=a0.y; AP[0][2]=a0.z;
        AP[1][0]=a0.w; AP[1][1]=a1.x; AP[1][2]=a1.y;
        AP[2][0]=a1.z; AP[2][1]=a1.w; AP[2][2]=a2.x;
        AP[3][0]=a2.y; AP[3][1]=a2.z; AP[3][2]=a2.w;
    } else {
#pragma unroll
        for (int at = 0; at < 4; at++) {
            int idx = i0 + at;
            bool v = (at < nval);
            kk[at] = v ? batch[idx] : (at ? kk[at - 1] : -1);
#pragma unroll
            for (int e = 0; e < 3; e++) {
                P[at][e]  = v ? pos[3 * idx + e] : 0.f;
                AP[at][e] = v ? atom_prop[3 * idx + e] : 0.f;
            }
        }
    }

    int gk[4];
#pragma unroll
    for (int at = 0; at < 4; at++) gk[at] = kk[at] < 0 ? 0 : kk[at];

    float hh[4][6];

    // ---- head: per-atom 9-feature vector ----
    float x[4][9];
#pragma unroll
    for (int at = 0; at < 4; at++) {
        const float4* civ = (const float4*)(g_cinv + gk[at] * 12);
        float4 c0 = civ[0], c1 = civ[1], c2 = civ[2];
        float ci[9] = {c0.x, c0.y, c0.z, c0.w, c1.x, c1.y, c1.z, c1.w, c2.x};
        float th[3];
#pragma unroll
        for (int e = 0; e < 3; e++) {
            float f = fmaf(P[at][0], ci[e], fmaf(P[at][1], ci[3 + e], P[at][2] * ci[6 + e]));
            th[e] = f - floorf(f) - 0.5f;
        }
        x[at][0] = AP[at][0]; x[at][1] = AP[at][1]; x[at][2] = AP[at][2];
#pragma unroll
        for (int j = 0; j < 3; j++) {
            float a = leaky(fmaf(sw0[j*3], AP[at][0], fmaf(sw0[j*3+1], AP[at][1], fmaf(sw0[j*3+2], AP[at][2], sb0[j]))));
            float u = fmaf(sw1[j*3], th[0], fmaf(sw1[j*3+1], th[1], fmaf(sw1[j*3+2], th[2], sb1[j])));
            float v = sb1n[j] - fmaf(sw1n[j*3], th[0], fmaf(sw1n[j*3+1], th[1], sw1n[j*3+2] * th[2]));
            x[at][3 + j] = fmaxf(u, 0.f) * a;
            x[at][6 + j] = fmaxf(v, 0.f) * a;
        }
    }

    // ---- layer-2 accumulators ----
    unsigned long long acc2[4][8];
#pragma unroll
    for (int q = 0; q < 8; q++) {
        unsigned long long bb = pack2(sb2b[2*q], sb2b[2*q+1]);
#pragma unroll
        for (int at = 0; at < 4; at++) acc2[at][q] = bb;
    }

    // ---- layer 1: four 8-output tiles, fused into layer 2 ----
#pragma unroll
    for (int jt = 0; jt < 4; jt++) {
        unsigned long long a1[4][4];
#pragma unroll
        for (int at = 0; at < 4; at++) {
            const float4* cv = (const float4*)(g_cvec + gk[at] * 32) + jt * 2;
            float4 c0 = cv[0], c1 = cv[1];
            a1[at][0] = pack2(c0.x, c0.y);
            a1[at][1] = pack2(c0.z, c0.w);
            a1[at][2] = pack2(c1.x, c1.y);
            a1[at][3] = pack2(c1.z, c1.w);
        }
#pragma unroll
        for (int k = 0; k < 9; k++) {
            const ulonglong2* wr = (const ulonglong2*)(sW1t + k * 32 + jt * 8);
            ulonglong2 wa = wr[0], wb = wr[1];
#pragma unroll
            for (int at = 0; at < 4; at++) {
                unsigned long long xd = pack2(x[at][k], x[at][k]);
                a1[at][0] = fma2(wa.x, xd, a1[at][0]);
                a1[at][1] = fma2(wa.y, xd, a1[at][1]);
                a1[at][2] = fma2(wb.x, xd, a1[at][2]);
                a1[at][3] = fma2(wb.y, xd, a1[at][3]);
            }
        }
        // fuse: relu(h1) -> layer 2
#pragma unroll
        for (int p = 0; p < 4; p++) {
            float h1v[4][2];
#pragma unroll
            for (int at = 0; at < 4; at++) {
                float lo, hi;
                unpack2(a1[at][p], lo, hi);
                h1v[at][0] = fmaxf(lo, 0.f);
                h1v[at][1] = fmaxf(hi, 0.f);
            }
#pragma unroll
            for (int r = 0; r < 2; r++) {
                int k2i = jt * 8 + 2 * p + r;
                const ulonglong2* wr = (const ulonglong2*)(sW2t + k2i * 16);
                ulonglong2 wA = wr[0], wB = wr[1], wC = wr[2], wD = wr[3];
#pragma unroll
                for (int at = 0; at < 4; at++) {
                    unsigned long long hd = pack2(h1v[at][r], h1v[at][r]);
                    acc2[at][0] = fma2(wA.x, hd, acc2[at][0]);
                    acc2[at][1] = fma2(wA.y, hd, acc2[at][1]);
                    acc2[at][2] = fma2(wB.x, hd, acc2[at][2]);
                    acc2[at][3] = fma2(wB.y, hd, acc2[at][3]);
                    acc2[at][4] = fma2(wC.x, hd, acc2[at][4]);
                    acc2[at][5] = fma2(wC.y, hd, acc2[at][5]);
                    acc2[at][6] = fma2(wD.x, hd, acc2[at][6]);
                    acc2[at][7] = fma2(wD.y, hd, acc2[at][7]);
                }
            }
        }
    }

    // ---- layer 3 fused from acc2 (6 outputs: 3 u64 accs) ----
    unsigned long long acc3[4][3];
#pragma unroll
    for (int q = 0; q < 3; q++) {
        unsigned long long bb = pack2(sb2c[2*q], sb2c[2*q+1]);
#pragma unroll
        for (int at = 0; at < 4; at++) acc3[at][q] = bb;
    }
#pragma unroll
    for (int p = 0; p < 8; p++) {
        float h2v[4][2];
#pragma unroll
        for (int at = 0; at < 4; at++) {
            float lo, hi;
            unpack2(acc2[at][p], lo, hi);
            h2v[at][0] = leaky(lo);
            h2v[at][1] = leaky(hi);
        }
#pragma unroll
        for (int r = 0; r < 2; r++) {
            int k3i = 2 * p + r;
            const ulonglong2* wr = (const ulonglong2*)(sW3t + k3i * 8);
            ulonglong2 wab = wr[0];
            unsigned long long wc = *(const unsigned long long*)(sW3t + k3i * 8 + 4);
#pragma unroll
            for (int at = 0; at < 4; at++) {
                unsigned long long hd = pack2(h2v[at][r], h2v[at][r]);
                acc3[at][0] = fma2(wab.x, hd, acc3[at][0]);
                acc3[at][1] = fma2(wab.y, hd, acc3[at][1]);
                acc3[at][2] = fma2(wc,    hd, acc3[at][2]);
            }
        }
    }
#pragma unroll
    for (int at = 0; at < 4; at++) {
#pragma unroll
        for (int q = 0; q < 3; q++)
            unpack2(acc3[at][q], hh[at][2*q], hh[at][2*q+1]);
    }
    if (!full) {
#pragma unroll
        for (int at = 0; at < 4; at++)
            if (at >= nval) {
#pragma unroll
                for (int k = 0; k < 6; k++) hh[at][k] = 0.f;
            }
    }

    // ---- segmented reduction: 4 sorted keys per thread ----
    int k0 = kk[0], k1 = kk[1], k2 = kk[2], k3 = kk[3];

    // trailing-run sum (scanned across warp)
    float s[6];
#pragma unroll
    for (int k = 0; k < 6; k++) {
        float t = hh[3][k];
        if (k2 == k3) {
            t += hh[2][k];
            if (k1 == k3) {
                t += hh[1][k];
                if (k0 == k3) t += hh[0][k];
            }
        }
        s[k] = t;
    }

    const unsigned mask = 0xffffffffu;
    unsigned mseg = __match_any_sync(mask, k3);
    int head = __ffs(mseg) - 1;
#pragma unroll
    for (int d = 1; d < 32; d <<= 1) {
        bool take = (lane >= head + d);
#pragma unroll
        for (int k = 0; k < 6; k++) {
            float o = __shfl_up_sync(mask, s[k], d);
            if (take) s[k] += o;
        }
    }

    int kprev = __shfl_up_sync(mask, k3, 1);
    float sprev[6];
#pragma unroll
    for (int k = 0; k < 6; k++) sprev[k] = __shfl_up_sync(mask, s[k], 1);
    int knext0 = __shfl_down_sync(mask, k0, 1);

    // first run ends inside thread
    if (k0 >= 0 && k0 != k3) {
        bool carry = (lane > 0) && (kprev == k0);
#pragma unroll
        for (int k = 0; k < 6; k++) {
            float f = hh[0][k];
            if (k1 == k0) f += hh[1][k];
            if (k2 == k0) f += hh[2][k];
            if (carry) f += sprev[k];
            atomicAdd(&out[k0 * 6 + k], f);
        }
    }
    // middle runs (fully inside thread)
    if (k1 >= 0 && k1 != k0 && k1 != k3) {
#pragma unroll
        for (int k = 0; k < 6; k++) {
            float f = hh[1][k];
            if (k2 == k1) f += hh[2][k];
            atomicAdd(&out[k1 * 6 + k], f);
        }
    }
    if (k2 >= 0 && k2 != k1 && k2 != k3) {
#pragma unroll
        for (int k = 0; k < 6; k++)
            atomicAdd(&out[k2 * 6 + k], hh[2][k]);
    }
    // trailing run flushed at segment tail
    bool tail = (lane == 31) || (knext0 != k3);
    if (k3 >= 0 && tail) {
#pragma unroll
        for (int k = 0; k < 6; k++)
            atomicAdd(&out[k3 * 6 + k], s[k]);
    }
}

extern "C" void kernel_launch(void* const* d_in, const int* in_sizes, int n_in,
                              void* d_out, int out_size)
{
    const float* atom_prop = (const float*)d_in[0];
    const float* pos       = (const float*)d_in[1];
    const float* cell      = (const float*)d_in[2];
    const int*   batch     = (const int*)d_in[3];
    const float* w0  = (const float*)d_in[4];
    const float* b0  = (const float*)d_in[5];
    const float* w1  = (const float*)d_in[6];
    const float* b1  = (const float*)d_in[7];
    const float* w1n = (const float*)d_in[8];
    const float* b1n = (const float*)d_in[9];
    const float* w2a = (const float*)d_in[10];
    const float* b2a = (const float*)d_in[11];
    const float* w2b = (const float*)d_in[12];
    const float* b2b = (const float*)d_in[13];
    const float* w2c = (const float*)d_in[14];
    const float* b2c = (const float*)d_in[15];
    float* out = (float*)d_out;

    int n = in_sizes[3];        // N_ATOMS
    int S = in_sizes[2] / 9;    // N_STRUCT

    precompute_kernel<<<(S + 7) / 8, 256>>>(cell, w2a, b2a, out, S);
    int atomsPerBlock = 128 * 4;
    atom_kernel<<<(n + atomsPerBlock - 1) / atomsPerBlock, 128>>>(
        atom_prop, pos, batch, w0, b0, w1, b1, w1n, b1n,
        w2a, w2b, b2b, w2c, b2c, out, n);
}